// round 1
// baseline (speedup 1.0000x reference)
#include <cuda_runtime.h>
#include <math.h>
#include <stdint.h>

#define Nq 8192
#define Kc 8192
#define Dd 512
#define Mq (2*Nq)

// ---------------- device scratch (static; no allocations) ----------------
__device__ float g_codebook[Kc*Dd];   // [K,D] projected codebook
__device__ float g_cbsq[Kc];          // ||c_k||^2
__device__ float g_bd[2*Mq];          // best dist per (ksplit,row)
__device__ int   g_bi[2*Mq];          // best idx  per (ksplit,row)
__device__ int   g_counts[2*Kc];      // histogram per source
__device__ float g_rowsums[Mq*2];     // per-row (mse_self, mse_cross) partial sums

// ---------------- reset (device globals persist across graph replays) ----
__global__ void reset_kernel() {
    int i = blockIdx.x * 256 + threadIdx.x;
    if (i < 2*Kc) g_counts[i] = 0;
}

// ---------------- codebook GEMM: C[k][d] = emb[k,:]·pw[d,:] + b[d] -------
__global__ __launch_bounds__(256) void codebook_gemm(
    const float* __restrict__ emb, const float* __restrict__ pw,
    const float* __restrict__ pb)
{
    __shared__ float Es[16][64];
    __shared__ float Ps[16][64];
    const int tid = threadIdx.x;
    const int tx = tid & 15, ty = tid >> 4;
    const int kb = blockIdx.x * 64, db = blockIdx.y * 64;
    const int lr = tid & 63, jq = tid >> 6;   // loader: row-in-tile, quad-of-16

    float acc[4][4];
    #pragma unroll
    for (int i = 0; i < 4; i++)
        #pragma unroll
        for (int j = 0; j < 4; j++) acc[i][j] = 0.f;

    for (int j0 = 0; j0 < Dd; j0 += 16) {
        float4 ve = *(const float4*)(emb + (size_t)(kb+lr)*Dd + j0 + jq*4);
        Es[jq*4+0][lr]=ve.x; Es[jq*4+1][lr]=ve.y; Es[jq*4+2][lr]=ve.z; Es[jq*4+3][lr]=ve.w;
        float4 vp = *(const float4*)(pw  + (size_t)(db+lr)*Dd + j0 + jq*4);
        Ps[jq*4+0][lr]=vp.x; Ps[jq*4+1][lr]=vp.y; Ps[jq*4+2][lr]=vp.z; Ps[jq*4+3][lr]=vp.w;
        __syncthreads();
        #pragma unroll
        for (int jj = 0; jj < 16; jj++) {
            float4 a = *(const float4*)&Es[jj][ty*4];
            float4 b = *(const float4*)&Ps[jj][tx*4];
            float ar[4] = {a.x,a.y,a.z,a.w};
            float br[4] = {b.x,b.y,b.z,b.w};
            #pragma unroll
            for (int i = 0; i < 4; i++)
                #pragma unroll
                for (int j = 0; j < 4; j++)
                    acc[i][j] = fmaf(ar[i], br[j], acc[i][j]);
        }
        __syncthreads();
    }
    #pragma unroll
    for (int j = 0; j < 4; j++) {
        float bias = pb[db + tx*4 + j];
        #pragma unroll
        for (int i = 0; i < 4; i++)
            g_codebook[(size_t)(kb + ty*4 + i)*Dd + db + tx*4 + j] = acc[i][j] + bias;
    }
}

// ---------------- cb_sq: one warp per codebook row ------------------------
__global__ void cbsq_kernel() {
    int row  = blockIdx.x * 8 + (threadIdx.x >> 5);
    int lane = threadIdx.x & 31;
    const float* c = g_codebook + (size_t)row * Dd;
    float s = 0.f;
    for (int d = lane*4; d < Dd; d += 128) {
        float4 v = *(const float4*)(c + d);
        s += v.x*v.x + v.y*v.y + v.z*v.z + v.w*v.w;
    }
    #pragma unroll
    for (int off = 16; off; off >>= 1) s += __shfl_down_sync(0xffffffffu, s, off);
    if (lane == 0) g_cbsq[row] = s;
}

// ---------------- argmin: 128x128 tile, 8x8/thread, K split 2-way ---------
#define BM 128
#define BN 128
#define BD 8
__global__ __launch_bounds__(256, 2) void argmin_kernel(
    const float* __restrict__ X0, const float* __restrict__ X1)
{
    __shared__ float Xs[BD][BM];
    __shared__ float Cs[BD][BN];
    __shared__ float sD[BM][16];
    __shared__ int   sI[BM][16];

    const int tid = threadIdx.x;
    const int tx = tid & 15, ty = tid >> 4;
    const int m0 = blockIdx.x * BM;
    const float* X = (m0 < Nq) ? (X0 + (size_t)m0*Dd) : (X1 + (size_t)(m0-Nq)*Dd);
    const int k0 = blockIdx.y * (Kc/2);
    const int ml = tid & 127, dq = tid >> 7;

    float bd[8]; int bi[8];
    #pragma unroll
    for (int i = 0; i < 8; i++) { bd[i] = INFINITY; bi[i] = 0; }

    for (int kc = 0; kc < Kc/2; kc += BN) {
        float acc[8][8];
        #pragma unroll
        for (int i = 0; i < 8; i++)
            #pragma unroll
            for (int j = 0; j < 8; j++) acc[i][j] = 0.f;

        for (int d0 = 0; d0 < Dd; d0 += BD) {
            float4 vx = *(const float4*)(X + (size_t)ml*Dd + d0 + dq*4);
            Xs[dq*4+0][ml]=vx.x; Xs[dq*4+1][ml]=vx.y; Xs[dq*4+2][ml]=vx.z; Xs[dq*4+3][ml]=vx.w;
            float4 vc = *(const float4*)(g_codebook + (size_t)(k0+kc+ml)*Dd + d0 + dq*4);
            Cs[dq*4+0][ml]=vc.x; Cs[dq*4+1][ml]=vc.y; Cs[dq*4+2][ml]=vc.z; Cs[dq*4+3][ml]=vc.w;
            __syncthreads();
            #pragma unroll
            for (int dd = 0; dd < BD; dd++) {
                float4 xa = *(const float4*)&Xs[dd][ty*4];
                float4 xb = *(const float4*)&Xs[dd][64 + ty*4];
                float4 ca = *(const float4*)&Cs[dd][tx*4];
                float4 cb = *(const float4*)&Cs[dd][64 + tx*4];
                float xr[8] = {xa.x,xa.y,xa.z,xa.w, xb.x,xb.y,xb.z,xb.w};
                float cr[8] = {ca.x,ca.y,ca.z,ca.w, cb.x,cb.y,cb.z,cb.w};
                #pragma unroll
                for (int i = 0; i < 8; i++)
                    #pragma unroll
                    for (int j = 0; j < 8; j++)
                        acc[i][j] = fmaf(xr[i], cr[j], acc[i][j]);
            }
            __syncthreads();
        }
        // epilogue: dist = cbsq - 2*dot ; running lexicographic min per row
        #pragma unroll
        for (int j = 0; j < 8; j++) {
            int cj = (j < 4) ? (tx*4 + j) : (64 + tx*4 + (j-4));
            int kk = k0 + kc + cj;
            float cq = g_cbsq[kk];
            #pragma unroll
            for (int i = 0; i < 8; i++) {
                float dist = fmaf(-2.f, acc[i][j], cq);
                if (dist < bd[i]) { bd[i] = dist; bi[i] = kk; }
            }
        }
    }

    // single cross-thread reduction at the end
    #pragma unroll
    for (int i = 0; i < 8; i++) {
        int ri = (i < 4) ? (ty*4 + i) : (64 + ty*4 + (i-4));
        sD[ri][tx] = bd[i]; sI[ri][tx] = bi[i];
    }
    __syncthreads();
    if (tid < BM) {
        float best = sD[tid][0]; int bidx = sI[tid][0];
        #pragma unroll
        for (int t = 1; t < 16; t++) {
            float dv = sD[tid][t]; int iv = sI[tid][t];
            if (dv < best || (dv == best && iv < bidx)) { best = dv; bidx = iv; }
        }
        g_bd[blockIdx.y*Mq + m0 + tid] = best;
        g_bi[blockIdx.y*Mq + m0 + tid] = bidx;
    }
}

// ---------------- finalize idx, gather row, per-row MSE partials ----------
__global__ void gather_kernel(const float* __restrict__ X0,
                              const float* __restrict__ X1,
                              float* __restrict__ out)
{
    const int m = blockIdx.x;
    const int tid = threadIdx.x;        // 128 threads, 4 floats each
    __shared__ int s_idx;
    __shared__ float wsum[4][2];

    if (tid == 0) {
        float d0 = g_bd[m], d1 = g_bd[Mq + m];
        int   i0 = g_bi[m], i1 = g_bi[Mq + m];
        int idx = (d1 < d0) ? i1 : i0;   // split0 always has the lower indices
        s_idx = idx;
        int src = (m < Nq) ? 0 : 1;
        atomicAdd(&g_counts[src*Kc + idx], 1);
    }
    __syncthreads();
    const int idx = s_idx;
    const float* q = g_codebook + (size_t)idx * Dd;
    const float *x, *o; float* op;
    if (m < Nq) { x = X0 + (size_t)m*Dd;      o = X1 + (size_t)m*Dd;      op = out + (size_t)m*Dd; }
    else { int mr = m - Nq;
           x = X1 + (size_t)mr*Dd;            o = X0 + (size_t)mr*Dd;     op = out + (size_t)(Nq+mr)*Dd; }

    float4 qv = *(const float4*)(q + tid*4);
    float4 xv = *(const float4*)(x + tid*4);
    float4 ov = *(const float4*)(o + tid*4);
    // straight-through forward value: x + (q - x), matching reference fp order
    float dx0 = qv.x - xv.x, dx1 = qv.y - xv.y, dx2 = qv.z - xv.z, dx3 = qv.w - xv.w;
    float4 w = {xv.x + dx0, xv.y + dx1, xv.z + dx2, xv.w + dx3};
    *(float4*)(op + tid*4) = w;

    float sA = dx0*dx0 + dx1*dx1 + dx2*dx2 + dx3*dx3;          // (q - x)^2
    float e0 = qv.x - ov.x, e1 = qv.y - ov.y, e2 = qv.z - ov.z, e3 = qv.w - ov.w;
    float sB = e0*e0 + e1*e1 + e2*e2 + e3*e3;                   // (q - other)^2
    #pragma unroll
    for (int off = 16; off; off >>= 1) {
        sA += __shfl_down_sync(0xffffffffu, sA, off);
        sB += __shfl_down_sync(0xffffffffu, sB, off);
    }
    int warp = tid >> 5, lane = tid & 31;
    if (lane == 0) { wsum[warp][0] = sA; wsum[warp][1] = sB; }
    __syncthreads();
    if (tid == 0) {
        g_rowsums[2*m]   = wsum[0][0] + wsum[1][0] + wsum[2][0] + wsum[3][0];
        g_rowsums[2*m+1] = wsum[0][1] + wsum[1][1] + wsum[2][1] + wsum[3][1];
    }
}

// ---------------- scalar losses (deterministic fixed-order reduce) --------
__global__ void loss_kernel(float* __restrict__ out) {
    const int t = threadIdx.x;   // 256
    __shared__ double red[4][256];
    double es = 0, csr = 0, er = 0, crs = 0;
    for (int m = t; m < Nq; m += 256)      { es  += (double)g_rowsums[2*m]; csr += (double)g_rowsums[2*m+1]; }
    for (int m = Nq + t; m < Mq; m += 256) { er  += (double)g_rowsums[2*m]; crs += (double)g_rowsums[2*m+1]; }
    red[0][t]=es; red[1][t]=csr; red[2][t]=er; red[3][t]=crs;
    __syncthreads();
    for (int off = 128; off; off >>= 1) {
        if (t < off) {
            red[0][t]+=red[0][t+off]; red[1][t]+=red[1][t+off];
            red[2][t]+=red[2][t+off]; red[3][t]+=red[3][t+off];
        }
        __syncthreads();
    }
    if (t == 0) {
        const double nd = (double)Nq * (double)Dd;
        double Es = red[0][0]/nd, Csr = red[1][0]/nd, Er = red[2][0]/nd, Crs = red[3][0]/nd;
        out[(size_t)2*Nq*Dd + 0] = (float)(0.5 * Es);                       // scRNA_loss
        double fwd = Er + Es + 0.5*Crs + 0.5*Csr;
        out[(size_t)2*Nq*Dd + 1] = (float)(0.5*Er + 0.25*fwd);              // ribo_loss
    }
}

// ---------------- perplexity per source -----------------------------------
__global__ void perp_kernel(float* __restrict__ out) {
    const int src = blockIdx.x;
    const int t = threadIdx.x;   // 256
    __shared__ float red[256];
    float h = 0.f;
    for (int k = t; k < Kc; k += 256) {
        float p = (float)g_counts[src*Kc + k] * (1.0f/(float)Nq);
        h += p * logf(p + 1e-10f);
    }
    red[t] = h;
    __syncthreads();
    for (int off = 128; off; off >>= 1) {
        if (t < off) red[t] += red[t+off];
        __syncthreads();
    }
    if (t == 0) out[(size_t)2*Nq*Dd + 2 + src] = expf(-red[0]);
}

// ---------------- launcher -------------------------------------------------
extern "C" void kernel_launch(void* const* d_in, const int* in_sizes, int n_in,
                              void* d_out, int out_size)
{
    const float* scRNA = (const float*)d_in[0];   // [N,D]
    const float* ribo  = (const float*)d_in[1];   // [N,D]
    const float* emb   = (const float*)d_in[2];   // [K,D]
    const float* pw    = (const float*)d_in[3];   // [D,D]
    const float* pb    = (const float*)d_in[4];   // [D]
    float* out = (float*)d_out;

    reset_kernel<<<(2*Kc + 255)/256, 256>>>();
    codebook_gemm<<<dim3(Kc/64, Dd/64), 256>>>(emb, pw, pb);
    cbsq_kernel<<<Kc/8, 256>>>();
    argmin_kernel<<<dim3(Mq/BM, 2), 256>>>(scRNA, ribo);
    gather_kernel<<<Mq, 128>>>(scRNA, ribo, out);
    loss_kernel<<<1, 256>>>(out);
    perp_kernel<<<2, 256>>>(out);
}